// round 15
// baseline (speedup 1.0000x reference)
#include <cuda_runtime.h>
#include <cuda_bf16.h>
#include <cstdint>

#define BS_   1024
#define NE_   128
#define EMB   512
#define NAG   32
#define NHD   8
#define HDD   64
#define KDIM  512

// ---------------- scratch (device globals; allocation-guard safe) ----------
// kv/q stored PACKED: row of N floats -> N u32 words; word 2p = bf16x2 hi of
// float pair (2p,2p+1) [low half = even dim], word 2p+1 = bf16x2 lo.
__device__ uint32_t g_kvp[(size_t)BS_ * NE_ * 1024]; // [b*128+e][K(512w)|V(512w)]
__device__ uint32_t g_qp [(size_t)BS_ * NAG * 512];
__device__ float    g_at[(size_t)BS_ * NAG * EMB];   // attention out (tf32-rounded)
__device__ float    g_wr[3 * EMB * KDIM];            // W_in, tf32-rounded
__device__ float    g_wor[EMB * EMB];                // W_out, tf32-rounded

// ---------------- helpers ----------------------------------------------------
#define CP16(dst, src) \
    asm volatile("cp.async.cg.shared.global [%0], [%1], 16;" :: "r"(dst), "l"(src) : "memory")
#define CP_COMMIT()  asm volatile("cp.async.commit_group;" ::: "memory")
#define CP_WAIT(n)   asm volatile("cp.async.wait_group %0;" :: "n"(n) : "memory")

__device__ __forceinline__ uint32_t smem_u32(const void* p) {
    uint32_t a;
    asm("{ .reg .u64 t; cvta.to.shared.u64 t, %1; cvt.u32.u64 %0, t; }" : "=r"(a) : "l"(p));
    return a;
}
__device__ __forceinline__ float f2tf32f(float f) {
    uint32_t r;
    asm("cvt.rna.tf32.f32 %0, %1;" : "=r"(r) : "f"(f));
    return __uint_as_float(r);
}
__device__ __forceinline__ uint32_t cvt_tf32_u32(uint32_t raw) {
    uint32_t r;
    asm("cvt.rna.tf32.f32 %0, %1;" : "=r"(r) : "f"(__uint_as_float(raw)));
    return r;
}
__device__ __forceinline__ void mma_tf32(float* c, const uint32_t* a, const uint32_t* b) {
    asm volatile(
        "mma.sync.aligned.m16n8k8.row.col.f32.tf32.tf32.f32 "
        "{%0,%1,%2,%3}, {%4,%5,%6,%7}, {%8,%9}, {%0,%1,%2,%3};"
        : "+f"(c[0]), "+f"(c[1]), "+f"(c[2]), "+f"(c[3])
        : "r"(a[0]), "r"(a[1]), "r"(a[2]), "r"(a[3]), "r"(b[0]), "r"(b[1]));
}
__device__ __forceinline__ void mma_bf16(float* c, const uint32_t* a, const uint32_t* b) {
    asm volatile(
        "mma.sync.aligned.m16n8k16.row.col.f32.bf16.bf16.f32 "
        "{%0,%1,%2,%3}, {%4,%5,%6,%7}, {%8,%9}, {%0,%1,%2,%3};"
        : "+f"(c[0]), "+f"(c[1]), "+f"(c[2]), "+f"(c[3])
        : "r"(a[0]), "r"(a[1]), "r"(a[2]), "r"(a[3]), "r"(b[0]), "r"(b[1]));
}
// split two fp32 into packed bf16x2 hi and lo words (low half = first arg)
__device__ __forceinline__ void split2(float x, float y, uint32_t& hi, uint32_t& lo) {
    asm("cvt.rn.bf16x2.f32 %0, %1, %2;" : "=r"(hi) : "f"(y), "f"(x));
    float hx = __uint_as_float(hi << 16);
    float hy = __uint_as_float(hi & 0xffff0000u);
    asm("cvt.rn.bf16x2.f32 %0, %1, %2;" : "=r"(lo) : "f"(y - hy), "f"(x - hx));
}

// ---------------- tf32 rounding pre-pass (weights only) ---------------------
__global__ __launch_bounds__(256)
void round_tf32(const float* __restrict__ x, float* __restrict__ y, int n4)
{
    int i = blockIdx.x * 256 + threadIdx.x;
    if (i >= n4) return;
    float4 v = ((const float4*)x)[i];
    v.x = f2tf32f(v.x); v.y = f2tf32f(v.y);
    v.z = f2tf32f(v.z); v.w = f2tf32f(v.w);
    ((float4*)y)[i] = v;
}

// ---------------- TF32 GEMM body (warp 64x64, frag pipeline) ----------------
// C = A[*,512] * B[*,512]^T. B pre-rounded tf32; A cvt'd in-register iff CVT_A.
// EPI 1: fp32 + bias + rowmask zero. EPI 2: packed bf16 hi/lo uint2 store
// (same addresses as the fp32 float2 would use; C reinterpreted as u32*).
#define FPITCH 36
#define ROWB   (FPITCH * 4)
#define MATB   (128 * ROWB)
#define STAGEB (2 * MATB)
#define NSTAGE 3

template<bool CVT_A, int EPI>
__device__ __forceinline__ void gemm_body(
    const float* __restrict__ A, const float* __restrict__ B,
    float* __restrict__ C, int ldc, int tm, int tn, bool remap,
    const float* __restrict__ bias, const int* __restrict__ rowmask,
    char* sm)
{
    const int tid  = threadIdx.x;
    const int wid  = tid >> 5, lane = tid & 31;
    const int wm   = wid >> 1, wn = wid & 1;
    const int lr4  = lane >> 2;
    const int lc   = lane & 3;

    const int rq = tid >> 2;
    const int qo = (tid & 3) << 2;

    const float* gA[4];
    const float* gB[4];
    #pragma unroll
    for (int k = 0; k < 4; k++) {
        int r = rq + 32 * k;
        int arow = tm * 128 + r;
        if (remap) arow = ((arow >> 5) << 7) | (arow & 31);
        gA[k] = A + (size_t)arow * KDIM + qo;
        gB[k] = B + (size_t)(tn * 128 + r) * KDIM + qo;
    }
    const uint32_t smb  = smem_u32(sm);
    const uint32_t dst0 = smb + rq * ROWB + qo * 4;

    float acc[4][8][4];
    #pragma unroll
    for (int i = 0; i < 4; i++)
        #pragma unroll
        for (int j = 0; j < 8; j++)
            #pragma unroll
            for (int k = 0; k < 4; k++) acc[i][j][k] = 0.f;

    auto issue = [&](int ch, int st) {
        const int koff = ch * 32;
        const uint32_t d = dst0 + st * STAGEB;
        #pragma unroll
        for (int k = 0; k < 4; k++) {
            const uint32_t dr = d + k * 32 * ROWB;
            CP16(dr,             gA[k] + koff);
            CP16(dr + 64,        gA[k] + koff + 16);
            CP16(dr + MATB,      gB[k] + koff);
            CP16(dr + MATB + 64, gB[k] + koff + 16);
        }
        CP_COMMIT();
    };

    issue(0, 0);
    issue(1, 1);

    const int warpRow = wm * 64;
    const int warpCol = wn * 64;

    uint32_t af[2][4][4], bf[2][8][2];

    #define LOAD_FRAGS(buf, ks, sA, sB) do {                                   \
        const int kb_ = (ks) * 32 + lc * 4;                                    \
        _Pragma("unroll")                                                      \
        for (int mt = 0; mt < 4; mt++) {                                       \
            int r_ = warpRow + mt * 16 + lr4;                                  \
            const char* p0_ = (sA) + r_ * ROWB + kb_;                          \
            const char* p1_ = (sA) + (r_ + 8) * ROWB + kb_;                    \
            uint32_t v0_ = *(const uint32_t*)p0_;                              \
            uint32_t v1_ = *(const uint32_t*)p1_;                              \
            uint32_t v2_ = *(const uint32_t*)(p0_ + 16);                       \
            uint32_t v3_ = *(const uint32_t*)(p1_ + 16);                       \
            if (CVT_A) {                                                       \
                v0_ = cvt_tf32_u32(v0_); v1_ = cvt_tf32_u32(v1_);              \
                v2_ = cvt_tf32_u32(v2_); v3_ = cvt_tf32_u32(v3_);              \
            }                                                                  \
            af[buf][mt][0] = v0_; af[buf][mt][1] = v1_;                        \
            af[buf][mt][2] = v2_; af[buf][mt][3] = v3_;                        \
        }                                                                      \
        _Pragma("unroll")                                                      \
        for (int nt = 0; nt < 8; nt++) {                                       \
            int c_ = warpCol + nt * 8 + lr4;                                   \
            const char* p_ = (sB) + c_ * ROWB + kb_;                           \
            bf[buf][nt][0] = *(const uint32_t*)p_;                             \
            bf[buf][nt][1] = *(const uint32_t*)(p_ + 16);                      \
        }                                                                      \
    } while (0)

    for (int ch = 0; ch < 16; ch++) {
        if (ch < 15) CP_WAIT(1); else CP_WAIT(0);
        __syncthreads();

        const int st = ch % NSTAGE;
        const char* sA = sm + st * STAGEB;
        const char* sB = sA + MATB;

        LOAD_FRAGS(0, 0, sA, sB);
        if (ch + 2 < 16) issue(ch + 2, (ch + 2) % 3);

        #pragma unroll
        for (int ks = 0; ks < 4; ks++) {
            const int cur = ks & 1;
            if (ks < 3) LOAD_FRAGS(cur ^ 1, ks + 1, sA, sB);
            #pragma unroll
            for (int mt = 0; mt < 4; mt++)
                #pragma unroll
                for (int nt = 0; nt < 8; nt++)
                    mma_tf32(acc[mt][nt], af[cur][mt], bf[cur][nt]);
        }
    }
    #undef LOAD_FRAGS

    #pragma unroll
    for (int mt = 0; mt < 4; mt++) {
        int r0 = tm * 128 + warpRow + mt * 16 + lr4;
        int r1 = r0 + 8;
        bool z0 = false, z1 = false;
        if (EPI == 1) { z0 = rowmask[r0] != 0; z1 = rowmask[r1] != 0; }
        #pragma unroll
        for (int nt = 0; nt < 8; nt++) {
            int c = tn * 128 + warpCol + nt * 8 + lc * 2;
            if (EPI == 2) {
                uint32_t* P = (uint32_t*)C;
                uint32_t h0, l0, h1, l1;
                split2(acc[mt][nt][0], acc[mt][nt][1], h0, l0);
                split2(acc[mt][nt][2], acc[mt][nt][3], h1, l1);
                *(uint2*)(P + (size_t)r0 * ldc + c) = make_uint2(h0, l0);
                *(uint2*)(P + (size_t)r1 * ldc + c) = make_uint2(h1, l1);
            } else {
                float2 v0 = make_float2(acc[mt][nt][0], acc[mt][nt][1]);
                float2 v1 = make_float2(acc[mt][nt][2], acc[mt][nt][3]);
                float2 bb = *(const float2*)(bias + c);
                if (z0) v0 = make_float2(0.f, 0.f);
                else    { v0.x += bb.x; v0.y += bb.y; }
                if (z1) v1 = make_float2(0.f, 0.f);
                else    { v1.x += bb.x; v1.y += bb.y; }
                *(float2*)(C + (size_t)r0 * ldc + c) = v0;
                *(float2*)(C + (size_t)r1 * ldc + c) = v1;
            }
        }
    }
}

__global__ __launch_bounds__(128, 2)
void gemm_kvq(const float* __restrict__ ent, const float* __restrict__ wr,
              uint32_t* __restrict__ kvp, uint32_t* __restrict__ qp)
{
    extern __shared__ char sm[];
    const int bx = blockIdx.x, by = blockIdx.y;
    if (by < 1024) {
        gemm_body<true, 2>(ent, wr + 512 * 512, (float*)kvp, 1024, by, bx, false,
                           nullptr, nullptr, sm);
    } else {
        int id = (by - 1024) * 8 + bx;
        gemm_body<true, 2>(ent, wr, (float*)qp, 512, id >> 2, id & 3, true,
                           nullptr, nullptr, sm);
    }
}

__global__ __launch_bounds__(128, 2)
void gemm_out(const float* __restrict__ A, const float* __restrict__ B,
              float* __restrict__ C,
              const float* __restrict__ bias, const int* __restrict__ rowmask)
{
    extern __shared__ char sm[];
    gemm_body<false, 1>(A, B, C, 512, blockIdx.y, blockIdx.x, false,
                        bias, rowmask, sm);
}

// ---------------- attention: bf16x3, packed producer-split operands ---------
// block = (b,h), 256 thr (8 warps, grid 2x4). q/k/v arrive as interleaved
// {hi,lo} word pairs (coalesced identical to fp32 float2 reads). No converts
// for q/k (plane deinterleave via addressing); v transpose via shfl+prmt.
#define OQH 0                    // qhi [32][36]
#define OQL 1152                 // qlo
#define OKH 2304                 // khi [128][36]
#define OKL 6912                 // klo          -> 11520
#define OVH 11520                // vt hi [64 d][68 e-pairs]
#define OVL 15872                // vt lo        -> 20224
#define OU  0                    // overlay: logits [32][132] = 4224
#define OWH 4224                 // overlay: w hi [32][68]
#define OWL 6400                 // overlay: w lo -> 8576 (< 11520, fits)
#define ATTN_WORDS 20224         // 80896 bytes

__global__ __launch_bounds__(256, 2)
void attn_kernel(const uint32_t* __restrict__ qp, const uint32_t* __restrict__ kvp,
                 const int* __restrict__ pre_mask, float* __restrict__ out)
{
    extern __shared__ uint32_t smw[];
    float* smf = (float*)smw;
    const int tid = threadIdx.x;
    const int wid = tid >> 5, lane = tid & 31;
    const int lr4 = lane >> 2, lc = lane & 3;
    const int wm  = wid >> 2, wn = wid & 3;          // warp grid 2x4
    const int b = blockIdx.x >> 3;
    const int h = blockIdx.x & 7;
    const int rowA = wm * 16 + lr4;

    const uint32_t* qbase = qp  + (size_t)b * (NAG * 512) + h * HDD;   // 64 words/row slice
    const uint32_t* kbase = kvp + (size_t)b * (NE_ * 1024) + h * HDD;
    const uint32_t* vbase = kbase + 512;

    // P0: prefetch pre-mask into registers
    const int* mb = pre_mask + (size_t)b * (NAG * NE_);
    int2 pm0[4], pm1[4];
    #pragma unroll
    for (int nt = 0; nt < 4; nt++) {
        int c = wn * 32 + nt * 8 + lc * 2;
        pm0[nt] = *(const int2*)(mb + rowA * NE_ + c);
        pm1[nt] = *(const int2*)(mb + (rowA + 8) * NE_ + c);
    }

    // P3: v -> transposed vt hi/lo via paired-lane shfl + prmt (no converts)
    #pragma unroll
    for (int it = 0; it < 16; it++) {
        int slot  = wid + it * 8;            // 0..127
        int epair = slot & 63;
        int fh    = slot >> 6;               // 0 or 1
        int dw    = fh * 16 + (lane >> 1);   // float-pair index 0..31
        int e     = 2 * epair + (lane & 1);
        uint2 x = *(const uint2*)(vbase + (size_t)e * 1024 + 2 * dw);  // {hi,lo}
        uint32_t yh = __shfl_xor_sync(0xffffffffu, x.x, 1);
        uint32_t yl = __shfl_xor_sync(0xffffffffu, x.y, 1);
        uint32_t hiE = (lane & 1) ? yh  : x.x;
        uint32_t hiO = (lane & 1) ? x.x : yh;
        uint32_t loE = (lane & 1) ? yl  : x.y;
        uint32_t loO = (lane & 1) ? x.y : yl;
        int d = 2 * dw + (lane & 1);
        uint32_t sel = (lane & 1) ? 0x7632u : 0x5410u;
        smw[OVH + d * 68 + epair] = __byte_perm(hiE, hiO, sel);
        smw[OVL + d * 68 + epair] = __byte_perm(loE, loO, sel);
    }
    // P1: q packed -> plane deinterleave (no converts)
    #pragma unroll
    for (int it = 0; it < 4; it++) {
        int i = tid + it * 256;
        int a = i >> 5, wd = i & 31;
        uint2 x = *(const uint2*)(qbase + (size_t)a * 512 + 2 * wd);
        smw[OQH + a * 36 + wd] = x.x;
        smw[OQL + a * 36 + wd] = x.y;
    }
    // P2: k packed -> plane deinterleave (no converts)
    #pragma unroll
    for (int it = 0; it < 16; it++) {
        int i = tid + it * 256;
        int e = i >> 5, wd = i & 31;
        uint2 x = *(const uint2*)(kbase + (size_t)e * 1024 + 2 * wd);
        smw[OKH + e * 36 + wd] = x.x;
        smw[OKL + e * 36 + wd] = x.y;
    }
    __syncthreads();

    // P4: logits = q @ k^T (bf16x3), warp tile 16a x 32e, K=64
    float lg[4][4];
    #pragma unroll
    for (int i = 0; i < 4; i++)
        #pragma unroll
        for (int j = 0; j < 4; j++) lg[i][j] = 0.f;

    #pragma unroll
    for (int ks = 0; ks < 4; ks++) {
        const int kw = lc + ks * 8;
        uint32_t ah[4], al[4];
        ah[0] = smw[OQH + rowA * 36 + kw];       al[0] = smw[OQL + rowA * 36 + kw];
        ah[1] = smw[OQH + (rowA + 8) * 36 + kw]; al[1] = smw[OQL + (rowA + 8) * 36 + kw];
        ah[2] = smw[OQH + rowA * 36 + kw + 4];   al[2] = smw[OQL + rowA * 36 + kw + 4];
        ah[3] = smw[OQH + (rowA + 8) * 36 + kw + 4]; al[3] = smw[OQL + (rowA + 8) * 36 + kw + 4];
        #pragma unroll
        for (int nt = 0; nt < 4; nt++) {
            int col = wn * 32 + nt * 8 + lr4;
            uint32_t bh[2], bl[2];
            bh[0] = smw[OKH + col * 36 + kw];     bh[1] = smw[OKH + col * 36 + kw + 4];
            bl[0] = smw[OKL + col * 36 + kw];     bl[1] = smw[OKL + col * 36 + kw + 4];
            mma_bf16(lg[nt], ah, bh);
            mma_bf16(lg[nt], ah, bl);
            mma_bf16(lg[nt], al, bh);
        }
    }
    __syncthreads();   // q/k reads complete before overlay writes below

    // P5: masked, scaled logits -> overlay smem (pitch 132), masks from regs
    {
        int r0 = rowA, r1 = rowA + 8;
        #pragma unroll
        for (int nt = 0; nt < 4; nt++) {
            int c = wn * 32 + nt * 8 + lc * 2;
            smf[OU + r0 * 132 + c]     = pm0[nt].x ? -1e30f : lg[nt][0] * 0.125f;
            smf[OU + r0 * 132 + c + 1] = pm0[nt].y ? -1e30f : lg[nt][1] * 0.125f;
            smf[OU + r1 * 132 + c]     = pm1[nt].x ? -1e30f : lg[nt][2] * 0.125f;
            smf[OU + r1 * 132 + c + 1] = pm1[nt].y ? -1e30f : lg[nt][3] * 0.125f;
        }
    }
    __syncthreads();

    // P6: softmax over e (8 threads per agent row)
    {
        int a = tid >> 3, l = tid & 7;
        float* row = smf + OU + a * 132;
        float mx = -1e30f;
        #pragma unroll
        for (int j = 0; j < 16; j++) mx = fmaxf(mx, row[l + 8 * j]);
        mx = fmaxf(mx, __shfl_xor_sync(0xffffffffu, mx, 1));
        mx = fmaxf(mx, __shfl_xor_sync(0xffffffffu, mx, 2));
        mx = fmaxf(mx, __shfl_xor_sync(0xffffffffu, mx, 4));
        float ex[16], sum = 0.f;
        #pragma unroll
        for (int j = 0; j < 16; j++) { float t = __expf(row[l + 8 * j] - mx); ex[j] = t; sum += t; }
        sum += __shfl_xor_sync(0xffffffffu, sum, 1);
        sum += __shfl_xor_sync(0xffffffffu, sum, 2);
        sum += __shfl_xor_sync(0xffffffffu, sum, 4);
        float inv = (mx <= -1e29f) ? 0.f : (1.0f / sum);
        #pragma unroll
        for (int j = 0; j < 16; j++) row[l + 8 * j] = ex[j] * inv;
    }
    __syncthreads();

    // P7: w -> whi/wlo bf16 pairs (overlay region; fp32 values born in-kernel)
    #pragma unroll
    for (int it = 0; it < 8; it++) {
        int i = tid + it * 256;
        int a = i >> 6, ep = i & 63;
        float2 x = *(const float2*)(smf + OU + a * 132 + 2 * ep);
        uint32_t hi, lo; split2(x.x, x.y, hi, lo);
        smw[OWH + a * 68 + ep] = hi;
        smw[OWL + a * 68 + ep] = lo;
    }
    __syncthreads();

    // P8: attn = w @ v (bf16x3), warp tile 16a x 16d, K=128
    float oa[2][4];
    #pragma unroll
    for (int i = 0; i < 2; i++)
        #pragma unroll
        for (int j = 0; j < 4; j++) oa[i][j] = 0.f;

    #pragma unroll
    for (int ks = 0; ks < 8; ks++) {
        const int kw = lc + ks * 8;
        uint32_t ah[4], al[4];
        ah[0] = smw[OWH + rowA * 68 + kw];           al[0] = smw[OWL + rowA * 68 + kw];
        ah[1] = smw[OWH + (rowA + 8) * 68 + kw];     al[1] = smw[OWL + (rowA + 8) * 68 + kw];
        ah[2] = smw[OWH + rowA * 68 + kw + 4];       al[2] = smw[OWL + rowA * 68 + kw + 4];
        ah[3] = smw[OWH + (rowA + 8) * 68 + kw + 4]; al[3] = smw[OWL + (rowA + 8) * 68 + kw + 4];
        #pragma unroll
        for (int nt = 0; nt < 2; nt++) {
            int col = wn * 16 + nt * 8 + lr4;
            uint32_t bh[2], bl[2];
            bh[0] = smw[OVH + col * 68 + kw];  bh[1] = smw[OVH + col * 68 + kw + 4];
            bl[0] = smw[OVL + col * 68 + kw];  bl[1] = smw[OVL + col * 68 + kw + 4];
            mma_bf16(oa[nt], ah, bh);
            mma_bf16(oa[nt], ah, bl);
            mma_bf16(oa[nt], al, bh);
        }
    }

    // P9: write attn out, tf32-rounded (out-GEMM A operand loads raw)
    float* ob = out + (size_t)b * (NAG * EMB) + h * HDD;
    #pragma unroll
    for (int nt = 0; nt < 2; nt++) {
        int d0 = wn * 16 + nt * 8 + lc * 2;
        *(float2*)(ob + (size_t)rowA * EMB + d0) =
            make_float2(f2tf32f(oa[nt][0]), f2tf32f(oa[nt][1]));
        *(float2*)(ob + (size_t)(rowA + 8) * EMB + d0) =
            make_float2(f2tf32f(oa[nt][2]), f2tf32f(oa[nt][3]));
    }
}

// ---------------- launch ---------------------------------------------------
extern "C" void kernel_launch(void* const* d_in, const int* in_sizes, int n_in,
                              void* d_out, int out_size)
{
    const float* entities  = (const float*)d_in[0];
    const int*   pre_mask  = (const int*)d_in[1];
    const int*   post_mask = (const int*)d_in[2];
    const float* W_in      = (const float*)d_in[3];
    const float* W_out     = (const float*)d_in[4];
    const float* b_out     = (const float*)d_in[5];
    float*       out       = (float*)d_out;

    float *at_p, *wr_p, *wor_p;
    uint32_t *kvp, *qp;
    cudaGetSymbolAddress((void**)&at_p,  g_at);
    cudaGetSymbolAddress((void**)&wr_p,  g_wr);
    cudaGetSymbolAddress((void**)&wor_p, g_wor);
    cudaGetSymbolAddress((void**)&kvp,   g_kvp);
    cudaGetSymbolAddress((void**)&qp,    g_qp);

    const int SMEM_BYTES = NSTAGE * STAGEB;       // 110592
    const int ATTN_BYTES = ATTN_WORDS * 4;        // 80896
    cudaFuncSetAttribute(gemm_kvq,    cudaFuncAttributeMaxDynamicSharedMemorySize, SMEM_BYTES);
    cudaFuncSetAttribute(gemm_out,    cudaFuncAttributeMaxDynamicSharedMemorySize, SMEM_BYTES);
    cudaFuncSetAttribute(attn_kernel, cudaFuncAttributeMaxDynamicSharedMemorySize, ATTN_BYTES);

    // tf32 rounding pre-pass (weights only; tiny)
    round_tf32<<<(3*EMB*KDIM/4 + 255)/256, 256>>>(W_in,  wr_p,  3*EMB*KDIM/4);
    round_tf32<<<(EMB*EMB/4    + 255)/256, 256>>>(W_out, wor_p, EMB*EMB/4);

    // merged K|V projection (y<1024) + Q projection (y>=1024); packed epilogue
    gemm_kvq<<<dim3(8, 1152), 128, SMEM_BYTES>>>(entities, wr_p, kvp, qp);

    // tensor-core attention (bf16x3; packed operands; writes tf32-rounded out)
    attn_kernel<<<BS_ * NHD, 256, ATTN_BYTES>>>(qp, kvp, pre_mask, at_p);

    // out GEMM + bias + post-mask
    gemm_out<<<dim3(4, 256), 128, SMEM_BYTES>>>(at_p, wor_p, out, b_out, post_mask);
}

// round 16
// speedup vs baseline: 1.0108x; 1.0108x over previous
#include <cuda_runtime.h>
#include <cuda_bf16.h>
#include <cstdint>

#define BS_   1024
#define NE_   128
#define EMB   512
#define NAG   32
#define NHD   8
#define HDD   64
#define KDIM  512

// ---------------- scratch (device globals; allocation-guard safe) ----------
__device__ float g_kv[(size_t)BS_ * NE_ * 1024];   // [b*128+e][K(512)|V(512)]
__device__ float g_q [(size_t)BS_ * NAG * EMB];
__device__ float g_at[(size_t)BS_ * NAG * EMB];    // attention out (tf32-rounded)
__device__ float g_wr[3 * EMB * KDIM];             // W_in, tf32-rounded
__device__ float g_wor[EMB * EMB];                 // W_out, tf32-rounded

// ---------------- helpers ----------------------------------------------------
#define CP16(dst, src) \
    asm volatile("cp.async.cg.shared.global [%0], [%1], 16;" :: "r"(dst), "l"(src) : "memory")
#define CP_COMMIT()  asm volatile("cp.async.commit_group;" ::: "memory")
#define CP_WAIT(n)   asm volatile("cp.async.wait_group %0;" :: "n"(n) : "memory")

__device__ __forceinline__ uint32_t smem_u32(const void* p) {
    uint32_t a;
    asm("{ .reg .u64 t; cvta.to.shared.u64 t, %1; cvt.u32.u64 %0, t; }" : "=r"(a) : "l"(p));
    return a;
}
__device__ __forceinline__ float f2tf32f(float f) {
    uint32_t r;
    asm("cvt.rna.tf32.f32 %0, %1;" : "=r"(r) : "f"(f));
    return __uint_as_float(r);
}
__device__ __forceinline__ uint32_t cvt_tf32_u32(uint32_t raw) {
    uint32_t r;
    asm("cvt.rna.tf32.f32 %0, %1;" : "=r"(r) : "f"(__uint_as_float(raw)));
    return r;
}
__device__ __forceinline__ void mma_tf32(float* c, const uint32_t* a, const uint32_t* b) {
    asm volatile(
        "mma.sync.aligned.m16n8k8.row.col.f32.tf32.tf32.f32 "
        "{%0,%1,%2,%3}, {%4,%5,%6,%7}, {%8,%9}, {%0,%1,%2,%3};"
        : "+f"(c[0]), "+f"(c[1]), "+f"(c[2]), "+f"(c[3])
        : "r"(a[0]), "r"(a[1]), "r"(a[2]), "r"(a[3]), "r"(b[0]), "r"(b[1]));
}
__device__ __forceinline__ void mma_bf16(float* c, const uint32_t* a, const uint32_t* b) {
    asm volatile(
        "mma.sync.aligned.m16n8k16.row.col.f32.bf16.bf16.f32 "
        "{%0,%1,%2,%3}, {%4,%5,%6,%7}, {%8,%9}, {%0,%1,%2,%3};"
        : "+f"(c[0]), "+f"(c[1]), "+f"(c[2]), "+f"(c[3])
        : "r"(a[0]), "r"(a[1]), "r"(a[2]), "r"(a[3]), "r"(b[0]), "r"(b[1]));
}
// split two fp32 into packed bf16x2 hi and lo words (low half = first arg)
__device__ __forceinline__ void split2(float x, float y, uint32_t& hi, uint32_t& lo) {
    asm("cvt.rn.bf16x2.f32 %0, %1, %2;" : "=r"(hi) : "f"(y), "f"(x));
    float hx = __uint_as_float(hi << 16);
    float hy = __uint_as_float(hi & 0xffff0000u);
    asm("cvt.rn.bf16x2.f32 %0, %1, %2;" : "=r"(lo) : "f"(y - hy), "f"(x - hx));
}

// ---------------- tf32 rounding pre-pass (both weight tensors, one launch) ---
#define WIN4  (3 * EMB * KDIM / 4)   // 196608 float4s
#define WOUT4 (EMB * EMB / 4)        // 65536 float4s
__global__ __launch_bounds__(256)
void round_weights(const float* __restrict__ win, float* __restrict__ wr,
                   const float* __restrict__ wout, float* __restrict__ wor)
{
    int i = blockIdx.x * 256 + threadIdx.x;
    const float* x; float* y; int idx;
    if (i < WIN4) { x = win; y = wr; idx = i; }
    else          { x = wout; y = wor; idx = i - WIN4; if (idx >= WOUT4) return; }
    float4 v = ((const float4*)x)[idx];
    v.x = f2tf32f(v.x); v.y = f2tf32f(v.y);
    v.z = f2tf32f(v.z); v.w = f2tf32f(v.w);
    ((float4*)y)[idx] = v;
}

// ---------------- TF32 GEMM body (warp 64x64, frag pipeline) ----------------
// C = A[*,512] * B[*,512]^T. B must be pre-rounded to tf32 patterns; A is
// cvt'd in-register iff CVT_A. CTA 128 thr (4 warps 2x2, each 64x64), BK=32,
// 3-stage cp.async ring, one barrier per chunk, 2-deep fragment pipeline.
#define FPITCH 36
#define ROWB   (FPITCH * 4)
#define MATB   (128 * ROWB)
#define STAGEB (2 * MATB)
#define NSTAGE 3

template<bool CVT_A>
__device__ __forceinline__ void gemm_body(
    const float* __restrict__ A, const float* __restrict__ B,
    float* __restrict__ C, int ldc, int tm, int tn, bool remap,
    bool final_, const float* __restrict__ bias, const int* __restrict__ rowmask,
    char* sm)
{
    const int tid  = threadIdx.x;
    const int wid  = tid >> 5, lane = tid & 31;
    const int wm   = wid >> 1, wn = wid & 1;
    const int lr4  = lane >> 2;
    const int lc   = lane & 3;

    const int rq = tid >> 2;
    const int qo = (tid & 3) << 2;

    const float* gA[4];
    const float* gB[4];
    #pragma unroll
    for (int k = 0; k < 4; k++) {
        int r = rq + 32 * k;
        int arow = tm * 128 + r;
        if (remap) arow = ((arow >> 5) << 7) | (arow & 31);
        gA[k] = A + (size_t)arow * KDIM + qo;
        gB[k] = B + (size_t)(tn * 128 + r) * KDIM + qo;
    }
    const uint32_t smb  = smem_u32(sm);
    const uint32_t dst0 = smb + rq * ROWB + qo * 4;

    float acc[4][8][4];
    #pragma unroll
    for (int i = 0; i < 4; i++)
        #pragma unroll
        for (int j = 0; j < 8; j++)
            #pragma unroll
            for (int k = 0; k < 4; k++) acc[i][j][k] = 0.f;

    auto issue = [&](int ch, int st) {
        const int koff = ch * 32;
        const uint32_t d = dst0 + st * STAGEB;
        #pragma unroll
        for (int k = 0; k < 4; k++) {
            const uint32_t dr = d + k * 32 * ROWB;
            CP16(dr,             gA[k] + koff);
            CP16(dr + 64,        gA[k] + koff + 16);
            CP16(dr + MATB,      gB[k] + koff);
            CP16(dr + MATB + 64, gB[k] + koff + 16);
        }
        CP_COMMIT();
    };

    issue(0, 0);
    issue(1, 1);

    const int warpRow = wm * 64;
    const int warpCol = wn * 64;

    uint32_t af[2][4][4], bf[2][8][2];

    #define LOAD_FRAGS(buf, ks, sA, sB) do {                                   \
        const int kb_ = (ks) * 32 + lc * 4;                                    \
        _Pragma("unroll")                                                      \
        for (int mt = 0; mt < 4; mt++) {                                       \
            int r_ = warpRow + mt * 16 + lr4;                                  \
            const char* p0_ = (sA) + r_ * ROWB + kb_;                          \
            const char* p1_ = (sA) + (r_ + 8) * ROWB + kb_;                    \
            uint32_t v0_ = *(const uint32_t*)p0_;                              \
            uint32_t v1_ = *(const uint32_t*)p1_;                              \
            uint32_t v2_ = *(const uint32_t*)(p0_ + 16);                       \
            uint32_t v3_ = *(const uint32_t*)(p1_ + 16);                       \
            if (CVT_A) {                                                       \
                v0_ = cvt_tf32_u32(v0_); v1_ = cvt_tf32_u32(v1_);              \
                v2_ = cvt_tf32_u32(v2_); v3_ = cvt_tf32_u32(v3_);              \
            }                                                                  \
            af[buf][mt][0] = v0_; af[buf][mt][1] = v1_;                        \
            af[buf][mt][2] = v2_; af[buf][mt][3] = v3_;                        \
        }                                                                      \
        _Pragma("unroll")                                                      \
        for (int nt = 0; nt < 8; nt++) {                                       \
            int c_ = warpCol + nt * 8 + lr4;                                   \
            const char* p_ = (sB) + c_ * ROWB + kb_;                           \
            bf[buf][nt][0] = *(const uint32_t*)p_;                             \
            bf[buf][nt][1] = *(const uint32_t*)(p_ + 16);                      \
        }                                                                      \
    } while (0)

    for (int ch = 0; ch < 16; ch++) {
        if (ch < 15) CP_WAIT(1); else CP_WAIT(0);
        __syncthreads();

        const int st = ch % NSTAGE;
        const char* sA = sm + st * STAGEB;
        const char* sB = sA + MATB;

        LOAD_FRAGS(0, 0, sA, sB);
        if (ch + 2 < 16) issue(ch + 2, (ch + 2) % 3);

        #pragma unroll
        for (int ks = 0; ks < 4; ks++) {
            const int cur = ks & 1;
            if (ks < 3) LOAD_FRAGS(cur ^ 1, ks + 1, sA, sB);
            #pragma unroll
            for (int mt = 0; mt < 4; mt++)
                #pragma unroll
                for (int nt = 0; nt < 8; nt++)
                    mma_tf32(acc[mt][nt], af[cur][mt], bf[cur][nt]);
        }
    }
    #undef LOAD_FRAGS

    #pragma unroll
    for (int mt = 0; mt < 4; mt++) {
        int r0 = tm * 128 + warpRow + mt * 16 + lr4;
        int r1 = r0 + 8;
        bool z0 = false, z1 = false;
        if (final_) { z0 = rowmask[r0] != 0; z1 = rowmask[r1] != 0; }
        #pragma unroll
        for (int nt = 0; nt < 8; nt++) {
            int c = tn * 128 + warpCol + nt * 8 + lc * 2;
            float2 v0 = make_float2(acc[mt][nt][0], acc[mt][nt][1]);
            float2 v1 = make_float2(acc[mt][nt][2], acc[mt][nt][3]);
            if (final_) {
                float2 bb = *(const float2*)(bias + c);
                if (z0) v0 = make_float2(0.f, 0.f);
                else    { v0.x += bb.x; v0.y += bb.y; }
                if (z1) v1 = make_float2(0.f, 0.f);
                else    { v1.x += bb.x; v1.y += bb.y; }
            }
            *(float2*)(C + (size_t)r0 * ldc + c) = v0;
            *(float2*)(C + (size_t)r1 * ldc + c) = v1;
        }
    }
}

__global__ __launch_bounds__(128, 2)
void gemm_kvq(const float* __restrict__ ent, const float* __restrict__ wr,
              float* __restrict__ kv, float* __restrict__ qo)
{
    extern __shared__ char sm[];
    const int bx = blockIdx.x, by = blockIdx.y;
    if (by < 1024) {
        gemm_body<true>(ent, wr + 512 * 512, kv, 1024, by, bx, false, false, nullptr, nullptr, sm);
    } else {
        int id = (by - 1024) * 8 + bx;
        gemm_body<true>(ent, wr, qo, 512, id >> 2, id & 3, true, false, nullptr, nullptr, sm);
    }
}

__global__ __launch_bounds__(128, 2)
void gemm_out(const float* __restrict__ A, const float* __restrict__ B,
              float* __restrict__ C,
              const float* __restrict__ bias, const int* __restrict__ rowmask)
{
    extern __shared__ char sm[];
    gemm_body<false>(A, B, C, 512, blockIdx.y, blockIdx.x, false, true, bias, rowmask, sm);
}

// ---------------- attention: bf16x3 tensor-core, overlaid smem --------------
// block = (b,h), 256 thr (8 warps, grid 2x4). 5 barriers total.
// q/k loads vectorized to float4 + paired uint2 STS.64 (bit-identical math).
#define OQH 0                    // qhi [32][36]
#define OQL 1152                 // qlo
#define OKH 2304                 // khi [128][36]
#define OKL 6912                 // klo          -> 11520
#define OVH 11520                // vt hi [64 d][68 e-pairs]
#define OVL 15872                // vt lo        -> 20224
#define OU  0                    // overlay: logits [32][132] = 4224
#define OWH 4224                 // overlay: w hi [32][68]
#define OWL 6400                 // overlay: w lo -> 8576 (< 11520, fits)
#define ATTN_WORDS 20224         // 80896 bytes

__global__ __launch_bounds__(256, 2)
void attn_kernel(const float* __restrict__ q, const float* __restrict__ kv,
                 const int* __restrict__ pre_mask, float* __restrict__ out)
{
    extern __shared__ uint32_t smw[];
    float* smf = (float*)smw;
    const int tid = threadIdx.x;
    const int wid = tid >> 5, lane = tid & 31;
    const int lr4 = lane >> 2, lc = lane & 3;
    const int wm  = wid >> 2, wn = wid & 3;          // warp grid 2x4
    const int b = blockIdx.x >> 3;
    const int h = blockIdx.x & 7;

    const float* qbase = q  + (size_t)b * (NAG * EMB) + h * HDD;
    const float* kbase = kv + (size_t)b * (NE_ * 1024) + h * HDD;
    const float* vbase = kbase + EMB;
    const int rowA = wm * 16 + lr4;

    // P0: prefetch pre-mask into registers (hides L2/DRAM latency)
    const int* mb = pre_mask + (size_t)b * (NAG * NE_);
    int2 pm0[4], pm1[4];
    #pragma unroll
    for (int nt = 0; nt < 4; nt++) {
        int c = wn * 32 + nt * 8 + lc * 2;
        pm0[nt] = *(const int2*)(mb + rowA * NE_ + c);
        pm1[nt] = *(const int2*)(mb + (rowA + 8) * NE_ + c);
    }

    // P3: v -> transposed vt hi/lo via paired-lane shuffle (longest chain first)
    #pragma unroll
    for (int it = 0; it < 16; it++) {
        int slot  = wid + it * 8;          // 0..127
        int epair = slot & 63;
        int fh    = slot >> 6;             // 0 or 1
        int f2    = fh * 16 + (lane >> 1); // 0..31 (float2 index along d)
        int e     = 2 * epair + (lane & 1);
        float2 x  = *(const float2*)(vbase + (size_t)e * 1024 + 2 * f2);
        float2 y;
        y.x = __shfl_xor_sync(0xffffffffu, x.x, 1);
        y.y = __shfl_xor_sync(0xffffffffu, x.y, 1);
        uint32_t hi, lo;
        int d;
        if (lane & 1) { split2(y.y, x.y, hi, lo); d = 2 * f2 + 1; }
        else          { split2(x.x, y.x, hi, lo); d = 2 * f2; }
        smw[OVH + d * 68 + epair] = hi;
        smw[OVL + d * 68 + epair] = lo;
    }
    // P1: q -> qhi/qlo (float4 loads, paired uint2 stores)
    #pragma unroll
    for (int it = 0; it < 2; it++) {
        int i = tid + it * 256;            // 0..511 of 32 rows x 16 float4
        int a = i >> 4, f4 = i & 15;
        float4 x = *(const float4*)(qbase + (size_t)a * EMB + f4 * 4);
        uint32_t h0, l0, h1, l1;
        split2(x.x, x.y, h0, l0);
        split2(x.z, x.w, h1, l1);
        int wd = f4 * 2;
        *(uint2*)&smw[OQH + a * 36 + wd] = make_uint2(h0, h1);
        *(uint2*)&smw[OQL + a * 36 + wd] = make_uint2(l0, l1);
    }
    // P2: k -> khi/klo (float4 loads, paired uint2 stores)
    #pragma unroll
    for (int it = 0; it < 8; it++) {
        int i = tid + it * 256;            // 0..2047 of 128 rows x 16 float4
        int e = i >> 4, f4 = i & 15;
        float4 x = *(const float4*)(kbase + (size_t)e * 1024 + f4 * 4);
        uint32_t h0, l0, h1, l1;
        split2(x.x, x.y, h0, l0);
        split2(x.z, x.w, h1, l1);
        int wd = f4 * 2;
        *(uint2*)&smw[OKH + e * 36 + wd] = make_uint2(h0, h1);
        *(uint2*)&smw[OKL + e * 36 + wd] = make_uint2(l0, l1);
    }
    __syncthreads();

    // P4: logits = q @ k^T (bf16x3), warp tile 16a x 32e, K=64
    float lg[4][4];
    #pragma unroll
    for (int i = 0; i < 4; i++)
        #pragma unroll
        for (int j = 0; j < 4; j++) lg[i][j] = 0.f;

    #pragma unroll
    for (int ks = 0; ks < 4; ks++) {
        const int kw = lc + ks * 8;
        uint32_t ah[4], al[4];
        ah[0] = smw[OQH + rowA * 36 + kw];       al[0] = smw[OQL + rowA * 36 + kw];
        ah[1] = smw[OQH + (rowA + 8) * 36 + kw]; al[1] = smw[OQL + (rowA + 8) * 36 + kw];
        ah[2] = smw[OQH + rowA * 36 + kw + 4];   al[2] = smw[OQL + rowA * 36 + kw + 4];
        ah[3] = smw[OQH + (rowA + 8) * 36 + kw + 4]; al[3] = smw[OQL + (rowA + 8) * 36 + kw + 4];
        #pragma unroll
        for (int nt = 0; nt < 4; nt++) {
            int col = wn * 32 + nt * 8 + lr4;
            uint32_t bh[2], bl[2];
            bh[0] = smw[OKH + col * 36 + kw];     bh[1] = smw[OKH + col * 36 + kw + 4];
            bl[0] = smw[OKL + col * 36 + kw];     bl[1] = smw[OKL + col * 36 + kw + 4];
            mma_bf16(lg[nt], ah, bh);
            mma_bf16(lg[nt], ah, bl);
            mma_bf16(lg[nt], al, bh);
        }
    }
    __syncthreads();   // q/k reads complete before overlay writes below

    // P5: masked, scaled logits -> overlay smem (pitch 132), masks from regs
    {
        int r0 = rowA, r1 = rowA + 8;
        #pragma unroll
        for (int nt = 0; nt < 4; nt++) {
            int c = wn * 32 + nt * 8 + lc * 2;
            smf[OU + r0 * 132 + c]     = pm0[nt].x ? -1e30f : lg[nt][0] * 0.125f;
            smf[OU + r0 * 132 + c + 1] = pm0[nt].y ? -1e30f : lg[nt][1] * 0.125f;
            smf[OU + r1 * 132 + c]     = pm1[nt].x ? -1e30f : lg[nt][2] * 0.125f;
            smf[OU + r1 * 132 + c + 1] = pm1[nt].y ? -1e30f : lg[nt][3] * 0.125f;
        }
    }
    __syncthreads();

    // P6: softmax over e (8 threads per agent row)
    {
        int a = tid >> 3, l = tid & 7;
        float* row = smf + OU + a * 132;
        float mx = -1e30f;
        #pragma unroll
        for (int j = 0; j < 16; j++) mx = fmaxf(mx, row[l + 8 * j]);
        mx = fmaxf(mx, __shfl_xor_sync(0xffffffffu, mx, 1));
        mx = fmaxf(mx, __shfl_xor_sync(0xffffffffu, mx, 2));
        mx = fmaxf(mx, __shfl_xor_sync(0xffffffffu, mx, 4));
        float ex[16], sum = 0.f;
        #pragma unroll
        for (int j = 0; j < 16; j++) { float t = __expf(row[l + 8 * j] - mx); ex[j] = t; sum += t; }
        sum += __shfl_xor_sync(0xffffffffu, sum, 1);
        sum += __shfl_xor_sync(0xffffffffu, sum, 2);
        sum += __shfl_xor_sync(0xffffffffu, sum, 4);
        float inv = (mx <= -1e29f) ? 0.f : (1.0f / sum);
        #pragma unroll
        for (int j = 0; j < 16; j++) row[l + 8 * j] = ex[j] * inv;
    }
    __syncthreads();

    // P7: w -> whi/wlo bf16 pairs (overlay region)
    #pragma unroll
    for (int it = 0; it < 8; it++) {
        int i = tid + it * 256;
        int a = i >> 6, ep = i & 63;
        float2 x = *(const float2*)(smf + OU + a * 132 + 2 * ep);
        uint32_t hi, lo; split2(x.x, x.y, hi, lo);
        smw[OWH + a * 68 + ep] = hi;
        smw[OWL + a * 68 + ep] = lo;
    }
    __syncthreads();

    // P8: attn = w @ v (bf16x3), warp tile 16a x 16d, K=128
    float oa[2][4];
    #pragma unroll
    for (int i = 0; i < 2; i++)
        #pragma unroll
        for (int j = 0; j < 4; j++) oa[i][j] = 0.f;

    #pragma unroll
    for (int ks = 0; ks < 8; ks++) {
        const int kw = lc + ks * 8;
        uint32_t ah[4], al[4];
        ah[0] = smw[OWH + rowA * 68 + kw];           al[0] = smw[OWL + rowA * 68 + kw];
        ah[1] = smw[OWH + (rowA + 8) * 68 + kw];     al[1] = smw[OWL + (rowA + 8) * 68 + kw];
        ah[2] = smw[OWH + rowA * 68 + kw + 4];       al[2] = smw[OWL + rowA * 68 + kw + 4];
        ah[3] = smw[OWH + (rowA + 8) * 68 + kw + 4]; al[3] = smw[OWL + (rowA + 8) * 68 + kw + 4];
        #pragma unroll
        for (int nt = 0; nt < 2; nt++) {
            int col = wn * 16 + nt * 8 + lr4;
            uint32_t bh[2], bl[2];
            bh[0] = smw[OVH + col * 68 + kw];  bh[1] = smw[OVH + col * 68 + kw + 4];
            bl[0] = smw[OVL + col * 68 + kw];  bl[1] = smw[OVL + col * 68 + kw + 4];
            mma_bf16(oa[nt], ah, bh);
            mma_bf16(oa[nt], ah, bl);
            mma_bf16(oa[nt], al, bh);
        }
    }

    // P9: write attn out, tf32-rounded (out-GEMM A operand loads raw)
    float* ob = out + (size_t)b * (NAG * EMB) + h * HDD;
    #pragma unroll
    for (int nt = 0; nt < 2; nt++) {
        int d0 = wn * 16 + nt * 8 + lc * 2;
        *(float2*)(ob + (size_t)rowA * EMB + d0) =
            make_float2(f2tf32f(oa[nt][0]), f2tf32f(oa[nt][1]));
        *(float2*)(ob + (size_t)(rowA + 8) * EMB + d0) =
            make_float2(f2tf32f(oa[nt][2]), f2tf32f(oa[nt][3]));
    }
}

// ---------------- launch ---------------------------------------------------
extern "C" void kernel_launch(void* const* d_in, const int* in_sizes, int n_in,
                              void* d_out, int out_size)
{
    const float* entities  = (const float*)d_in[0];
    const int*   pre_mask  = (const int*)d_in[1];
    const int*   post_mask = (const int*)d_in[2];
    const float* W_in      = (const float*)d_in[3];
    const float* W_out     = (const float*)d_in[4];
    const float* b_out     = (const float*)d_in[5];
    float*       out       = (float*)d_out;

    float *kv_p, *q_p, *at_p, *wr_p, *wor_p;
    cudaGetSymbolAddress((void**)&kv_p,  g_kv);
    cudaGetSymbolAddress((void**)&q_p,   g_q);
    cudaGetSymbolAddress((void**)&at_p,  g_at);
    cudaGetSymbolAddress((void**)&wr_p,  g_wr);
    cudaGetSymbolAddress((void**)&wor_p, g_wor);

    const int SMEM_BYTES = NSTAGE * STAGEB;       // 110592
    const int ATTN_BYTES = ATTN_WORDS * 4;        // 80896
    cudaFuncSetAttribute(gemm_kvq,    cudaFuncAttributeMaxDynamicSharedMemorySize, SMEM_BYTES);
    cudaFuncSetAttribute(gemm_out,    cudaFuncAttributeMaxDynamicSharedMemorySize, SMEM_BYTES);
    cudaFuncSetAttribute(attn_kernel, cudaFuncAttributeMaxDynamicSharedMemorySize, ATTN_BYTES);

    // tf32 rounding pre-pass (both weight tensors, single launch)
    round_weights<<<(WIN4 + WOUT4 + 255) / 256, 256>>>(W_in, wr_p, W_out, wor_p);

    // merged K|V projection (y<1024) + Q projection (y>=1024)
    gemm_kvq<<<dim3(8, 1152), 128, SMEM_BYTES>>>(entities, wr_p, kv_p, q_p);

    // tensor-core attention (bf16x3; writes tf32-rounded output)
    attn_kernel<<<BS_ * NHD, 256, ATTN_BYTES>>>(q_p, kv_p, pre_mask, at_p);

    // out GEMM + bias + post-mask (no A cvt needed)
    gemm_out<<<dim3(4, 256), 128, SMEM_BYTES>>>(at_p, wor_p, out, b_out, post_mask);
}